// round 10
// baseline (speedup 1.0000x reference)
#include <cuda_runtime.h>
#include <cstdint>

#define SEQ    512
#define BATCH  1024
#define NTAG   64

__device__ __forceinline__ float ex2f_(float x) {
    float y; asm("ex2.approx.ftz.f32 %0, %1;" : "=f"(y) : "f"(x)); return y;
}
__device__ __forceinline__ float lg2f_(float x) {
    float y; asm("lg2.approx.ftz.f32 %0, %1;" : "=f"(y) : "f"(x)); return y;
}
__device__ __forceinline__ unsigned long long fma2_(unsigned long long a,
                                                    unsigned long long b,
                                                    unsigned long long c) {
    unsigned long long d;
    asm("fma.rn.f32x2 %0, %1, %2, %3;" : "=l"(d) : "l"(a), "l"(b), "l"(c));
    return d;
}
__device__ __forceinline__ unsigned long long add2_(unsigned long long a,
                                                    unsigned long long b) {
    unsigned long long d;
    asm("add.rn.f32x2 %0, %1, %2;" : "=l"(d) : "l"(a), "l"(b));
    return d;
}
__device__ __forceinline__ void unpack_(unsigned long long v, float& x, float& y) {
    asm("mov.b64 {%0, %1}, %2;" : "=f"(x), "=f"(y) : "l"(v));
}
__device__ __forceinline__ unsigned long long pack_(float x, float y) {
    unsigned long long r;
    asm("mov.b64 %0, {%1, %2};" : "=l"(r) : "f"(x), "f"(y));
    return r;
}
__device__ __forceinline__ float wmax_(float v) {
#pragma unroll
    for (int d = 16; d; d >>= 1)
        v = fmaxf(v, __shfl_xor_sync(0xffffffffu, v, d));
    return v;
}

// One CTA = 64 threads = ONE batch, split as:
//   warp 0 (forward):  p_{t+1} = e^{f_t - SH} ∘ (E  p_t),   t = 0 .. h-1
//   warp 1 (backward): z_{t}   = E^T (e^{f_t - SH} ∘ z_{t+1}), t = len-1 .. h
// with the exact identity out = log( <p_h, z_h> ) + ledgers. Halves the
// sequential depth per warp and doubles warp count to 2048. Hot substep is
// unchanged from R8 (LDS broadcast -> FFMA2 matvec -> mul -> STS -> syncwarp,
// no per-step collectives); renorm once per 4 steps with 3 substeps of slack.
__global__ void __launch_bounds__(64, 5)
crf_main(const float* __restrict__ feats,
         const float* __restrict__ mask,
         const float* __restrict__ trans,
         float* __restrict__ out) {
    const int lane = threadIdx.x & 31;
    const int w    = threadIdx.x >> 5;        // 0 = forward, 1 = backward
    const int b    = blockIdx.x;

    __shared__ __align__(16) float pbuf[2][2][NTAG];   // [warp][phase][tag]
    __shared__ float vfin[2][2][32];                   // final vectors
    __shared__ float c2s[2];

    const float LN2 = 0.6931471805599453f;
    const float L2E = 1.4426950408889634f;
    const float SH2 = 6.0f * L2E;             // constant per-step down-scale

    // ---- len = sum of this batch's monotone mask column ----
    float lsum = 0.0f;
#pragma unroll
    for (int t = 0; t < 16; ++t)
        lsum += __ldcs(mask + (size_t)(t * 32 + lane) * BATCH + b);
#pragma unroll
    for (int d = 16; d; d >>= 1)
        lsum += __shfl_xor_sync(0xffffffffu, lsum, d);
    const int len  = (int)(lsum + 0.5f);
    const int h    = (len + 1) >> 1;
    const int nst  = w ? (len - h) : h;       // my step count (>=128 always)
    const int lenr = (nst + 3) & ~3;

    // ---- E (forward: rows of exp(T)) or E^T (backward: cols) in registers --
    const int s1 = w ? 1 : NTAG;              // trans[lane*s1 + j*s2]
    const int s2 = w ? NTAG : 1;
    unsigned long long EL[32], EH[32];
#pragma unroll
    for (int k = 0; k < 32; ++k) {
        EL[k] = pack_(__expf(__ldg(trans + lane * s1 + (2 * k) * s2)),
                      __expf(__ldg(trans + lane * s1 + (2 * k + 1) * s2)));
        EH[k] = pack_(__expf(__ldg(trans + (lane + 32) * s1 + (2 * k) * s2)),
                      __expf(__ldg(trans + (lane + 32) * s1 + (2 * k + 1) * s2)));
    }

    // ---- feats pipeline (direction-dependent) ----
    const float* fs    = feats + (size_t)b * NTAG + lane;   // step s at +s*65536
    const int    f0    = w ? len - 2 : 0;     // ef stream start for the loop
    const int    dstep = w ? -1 : 1;
    float efL[4], efH[4], fL[4], fH[4];
#pragma unroll
    for (int u = 0; u < 4; ++u) {
        const float* p0 = fs + ((size_t)(f0 + dstep * u) << 16);
        efL[u] = ex2f_(fmaf(__ldcs(p0),      L2E, -SH2));
        efH[u] = ex2f_(fmaf(__ldcs(p0 + 32), L2E, -SH2));
        const float* p1 = fs + ((size_t)(f0 + dstep * (u + 4)) << 16);
        fL[u] = __ldcs(p1);
        fH[u] = __ldcs(p1 + 32);
    }
    int fidx = f0 + dstep * 8;                // stays in [0, SEQ-1] (len>=256)

    // ---- initial published vector ----
    float v_lo, v_hi;
    if (w == 0) {                              // p_0 = one-hot at START=0
        v_lo = (lane == 0) ? 1.0f : 0.0f;
        v_hi = 0.0f;
    } else {                                   // v_0 = e^{f_{len-1}-SH} ∘ e^{T[END,:]}
        const float* pl = fs + ((size_t)(len - 1) << 16);
        const float fl = __ldcs(pl), fh = __ldcs(pl + 32);
        v_lo = ex2f_(trans[NTAG + lane] * L2E)      * ex2f_(fmaf(fl, L2E, -SH2));
        v_hi = ex2f_(trans[NTAG + 32 + lane] * L2E) * ex2f_(fmaf(fh, L2E, -SH2));
    }
    float st_lo = v_lo, st_hi = v_hi;          // state (overwritten at t=0)
    pbuf[w][0][lane]      = v_lo;
    pbuf[w][0][lane + 32] = v_hi;
    __syncwarp();

    float C2 = 0.0f, rfac = 1.0f, lgMp = 0.0f;

#pragma unroll 1
    for (int s = 0; s < lenr; s += 4) {
#pragma unroll
        for (int u = 0; u < 4; ++u) {
            const int ph = u & 1;

            // S = (E or E^T) v : 16 LDS.128 broadcast + 64 FFMA2
            const ulonglong2* pb =
                reinterpret_cast<const ulonglong2*>(&pbuf[w][ph][0]);
            unsigned long long x0 = 0ull, x1 = 0ull, x2 = 0ull, x3 = 0ull;
            unsigned long long y0 = 0ull, y1 = 0ull, y2 = 0ull, y3 = 0ull;
#pragma unroll
            for (int k = 0; k < 8; ++k) {
                const ulonglong2 qa = pb[2 * k];
                const ulonglong2 qb = pb[2 * k + 1];
                x0 = fma2_(EL[4 * k],     qa.x, x0);
                x1 = fma2_(EL[4 * k + 1], qa.y, x1);
                y0 = fma2_(EH[4 * k],     qa.x, y0);
                y1 = fma2_(EH[4 * k + 1], qa.y, y1);
                x2 = fma2_(EL[4 * k + 2], qb.x, x2);
                x3 = fma2_(EL[4 * k + 3], qb.y, x3);
                y2 = fma2_(EH[4 * k + 2], qb.x, y2);
                y3 = fma2_(EH[4 * k + 3], qb.y, y3);
            }
            float s0, s1f, s2f, s3;
            unpack_(add2_(add2_(x0, x1), add2_(x2, x3)), s0, s1f);
            unpack_(add2_(add2_(y0, y1), add2_(y2, y3)), s2f, s3);

            const bool  upd = (s + u) < nst;
            const float rr  = (u == 2) ? rfac : 1.0f;
            const float Sr_lo = (s0 + s1f) * rr;
            const float Sr_hi = (s2f + s3) * rr;
            const float pub_lo = Sr_lo * efL[u];     // next published vector
            const float pub_hi = Sr_hi * efH[u];
            // state: forward keeps the post-ef vector; backward keeps pure S
            const float cand_lo = w ? Sr_lo : pub_lo;
            const float cand_hi = w ? Sr_hi : pub_hi;
            st_lo = upd ? cand_lo : st_lo;
            st_hi = upd ? cand_hi : st_hi;
            C2 = upd ? (C2 + SH2 + ((u == 2) ? lgMp : 0.0f)) : C2;

            pbuf[w][ph ^ 1][lane]      = pub_lo;
            pbuf[w][ph ^ 1][lane + 32] = pub_hi;
            __syncwarp();

            // off-chain: feats pipeline (consumed 4 substeps later)
            efL[u] = ex2f_(fmaf(fL[u], L2E, -SH2));
            efH[u] = ex2f_(fmaf(fH[u], L2E, -SH2));
            const float* pf = fs + ((size_t)fidx << 16);
            fL[u] = __ldcs(pf);
            fH[u] = __ldcs(pf + 32);
            fidx += dstep;

            // once per 4 steps: renorm measured here, applied next block @u==2
            if (u == 3) {
                const float M   = fmaxf(wmax_(fmaxf(pub_lo, pub_hi)), 1e-30f);
                const float lgM = lg2f_(M);
                rfac = ex2f_(-lgM);
                lgMp = lgM;
            }
        }
    }

    // ---- combine: out = (C2f + C2b + lg2 <p_h, z_h>) * ln2 ----
    vfin[w][0][lane] = st_lo;
    vfin[w][1][lane] = st_hi;
    if (lane == 0) c2s[w] = C2;
    __syncthreads();
    if (w == 0) {
        float ss = st_lo * vfin[1][0][lane] + st_hi * vfin[1][1][lane];
#pragma unroll
        for (int d = 16; d; d >>= 1)
            ss += __shfl_xor_sync(0xffffffffu, ss, d);
        if (lane == 0)
            out[b] = (c2s[0] + c2s[1] + lg2f_(ss)) * LN2;
    }
}

extern "C" void kernel_launch(void* const* d_in, const int* in_sizes, int n_in,
                              void* d_out, int out_size) {
    const float* feats = nullptr;
    const float* maskp = nullptr;
    const float* trans = nullptr;
    for (int i = 0; i < n_in; ++i) {
        if (in_sizes[i] == SEQ * BATCH * NTAG)      feats = (const float*)d_in[i];
        else if (in_sizes[i] == SEQ * BATCH)        maskp = (const float*)d_in[i];
        else if (in_sizes[i] == NTAG * NTAG)        trans = (const float*)d_in[i];
    }
    crf_main<<<BATCH, 64>>>(feats, maskp, trans, (float*)d_out);
}

// round 11
// speedup vs baseline: 1.3831x; 1.3831x over previous
#include <cuda_runtime.h>
#include <cstdint>

#define SEQ    512
#define BATCH  1024
#define NTAG   64

__device__ __forceinline__ float ex2f_(float x) {
    float y; asm("ex2.approx.ftz.f32 %0, %1;" : "=f"(y) : "f"(x)); return y;
}
__device__ __forceinline__ float lg2f_(float x) {
    float y; asm("lg2.approx.ftz.f32 %0, %1;" : "=f"(y) : "f"(x)); return y;
}
__device__ __forceinline__ float wmax_(float v) {
#pragma unroll
    for (int d = 16; d; d >>= 1)
        v = fmaxf(v, __shfl_xor_sync(0xffffffffu, v, d));
    return v;
}

// One warp = one batch, 4 warps/CTA, NO shared memory in the hot loop.
// LINEAR-space recurrence p' = e^{f-SH} ∘ (E p) with log2 ledger C2 (R8 math).
// The all-to-all inside the matvec is done entirely with SHFL.BFLY:
//   for r = 0..31:  lane ^ r enumerates every lane, so
//   S_j = sum_r E[j][lane^r] * shfl_xor(p, r)  (E stored pre-permuted per lane)
// Hot step = 64 SHFL (independent, pipelined) + 128 FFMA, no STS/LDS/sync.
// Renorm once per 4 steps (measured u==3, applied next block u==2, 3 substeps
// of slack); constant SHIFT bounds drift between renorms (fp32-safe).
__global__ void __launch_bounds__(128)
crf_main(const float* __restrict__ feats,
         const float* __restrict__ mask,
         const float* __restrict__ trans,
         float* __restrict__ out) {
    const int lane = threadIdx.x & 31;
    const int w    = threadIdx.x >> 5;
    const int b    = blockIdx.x * 4 + w;

    const float LN2 = 0.6931471805599453f;
    const float L2E = 1.4426950408889634f;
    const float SH2 = 6.0f * L2E;             // constant per-step down-scale (log2)

    // ---- feats pipeline: ready e^{f-SH} (steps 0..3) + raw f (4..7) ----
    const float* fs    = feats + (size_t)b * NTAG + lane;   // step s at +s*65536
    const float* flast = fs + ((size_t)(SEQ - 1) << 16);
    float efL[4], efH[4], fL[4], fH[4];
#pragma unroll
    for (int u = 0; u < 4; ++u) {
        const float* p0 = fs + ((size_t)u << 16);
        efL[u] = ex2f_(fmaf(__ldcs(p0),      L2E, -SH2));
        efH[u] = ex2f_(fmaf(__ldcs(p0 + 32), L2E, -SH2));
        const float* p1 = fs + ((size_t)(u + 4) << 16);
        fL[u] = __ldcs(p1);
        fH[u] = __ldcs(p1 + 32);
    }
    const float* fpre = fs + ((size_t)8 << 16);

    // ---- len = sum of this batch's monotone mask column ----
    float lsum = 0.0f;
#pragma unroll
    for (int t = 0; t < 16; ++t)
        lsum += __ldcs(mask + (size_t)(t * 32 + lane) * BATCH + b);
#pragma unroll
    for (int d = 16; d; d >>= 1)
        lsum += __shfl_xor_sync(0xffffffffu, lsum, d);
    const int len  = (int)(lsum + 0.5f);
    const int lenr = (len + 3) & ~3;

    // ---- E pre-permuted for the butterfly: slot r holds E[j][lane^r] ----
    // EA[r] = exp(T[lane   ][lane^r])        (S_lo contribution from p_lo)
    // EB[r] = exp(T[lane+32][lane^r])        (S_hi contribution from p_lo)
    // EC[r] = exp(T[lane   ][32 + (lane^r)]) (S_lo contribution from p_hi)
    // ED[r] = exp(T[lane+32][32 + (lane^r)]) (S_hi contribution from p_hi)
    float EA[32], EB[32], EC[32], ED[32];
#pragma unroll
    for (int r = 0; r < 32; ++r) {
        const int i = lane ^ r;
        EA[r] = __expf(__ldg(trans + lane * NTAG + i));          // exp(-1e4)->0
        EB[r] = __expf(__ldg(trans + (lane + 32) * NTAG + i));
        EC[r] = __expf(__ldg(trans + lane * NTAG + 32 + i));
        ED[r] = __expf(__ldg(trans + (lane + 32) * NTAG + 32 + i));
    }
    const float eT_lo = ex2f_(trans[NTAG + lane] * L2E);         // exp(T[END][j])
    const float eT_hi = ex2f_(trans[NTAG + 32 + lane] * L2E);

    // ---- linear-space state (registers only) ----
    float p_lo = (lane == 0) ? 1.0f : 0.0f;   // p = exp(alpha0), START=0
    float p_hi = 0.0f;
    float C2   = 0.0f;                        // alpha = (log2 p + C2) * ln2
    float rfac = 1.0f;                        // renorm scale, applied at u==2
    float lgMp = 0.0f;                        // its lg2(M) ledger entry

#pragma unroll 1
    for (int s = 0; s < lenr; s += 4) {
#pragma unroll
        for (int u = 0; u < 4; ++u) {
            // S = E p via 32 butterflies: 64 SHFL + 128 FFMA, 8 acc chains
            float a0 = 0.f, a1 = 0.f, a2 = 0.f, a3 = 0.f;   // S_lo partials
            float b0 = 0.f, b1 = 0.f, b2 = 0.f, b3 = 0.f;   // S_hi partials
#pragma unroll
            for (int r = 0; r < 32; r += 2) {
                const float pl0 = __shfl_xor_sync(0xffffffffu, p_lo, r);
                const float ph0 = __shfl_xor_sync(0xffffffffu, p_hi, r);
                a0 = fmaf(EA[r], pl0, a0);
                b0 = fmaf(EB[r], pl0, b0);
                a1 = fmaf(EC[r], ph0, a1);
                b1 = fmaf(ED[r], ph0, b1);
                const float pl1 = __shfl_xor_sync(0xffffffffu, p_lo, r + 1);
                const float ph1 = __shfl_xor_sync(0xffffffffu, p_hi, r + 1);
                a2 = fmaf(EA[r + 1], pl1, a2);
                b2 = fmaf(EB[r + 1], pl1, b2);
                a3 = fmaf(EC[r + 1], ph1, a3);
                b3 = fmaf(ED[r + 1], ph1, b3);
            }
            const float S_lo = (a0 + a1) + (a2 + a3);
            const float S_hi = (b0 + b1) + (b2 + b3);

            // p' = e^{f-SH} ∘ S, renorm folded in at substep 2 only
            const bool  upd = (s + u) < len;
            const float rr  = (u == 2) ? rfac : 1.0f;
            const float n_lo = S_lo * (efL[u] * rr);
            const float n_hi = S_hi * (efH[u] * rr);
            p_lo = upd ? n_lo : p_lo;
            p_hi = upd ? n_hi : p_hi;
            C2   = upd ? (C2 + SH2 + ((u == 2) ? lgMp : 0.0f)) : C2;

            // off-chain: feats pipeline (consumed 4 substeps later)
            efL[u] = ex2f_(fmaf(fL[u], L2E, -SH2));
            efH[u] = ex2f_(fmaf(fH[u], L2E, -SH2));
            const float* pf = (fpre <= flast) ? fpre : flast;
            fL[u] = __ldcs(pf);
            fH[u] = __ldcs(pf + 32);
            fpre += (size_t)1 << 16;

            // once per 4 steps: renorm measured here, applied next block @u==2
            if (u == 3) {
                const float M   = fmaxf(wmax_(fmaxf(p_lo, p_hi)), 1e-30f);
                const float lgM = lg2f_(M);
                rfac = ex2f_(-lgM);
                lgMp = lgM;
            }
        }
    }

    // out[b] = (C2 + lg2( sum_j p_j * exp(T[END][j]) )) * ln2
    float ss = p_lo * eT_lo + p_hi * eT_hi;
#pragma unroll
    for (int d = 16; d; d >>= 1)
        ss += __shfl_xor_sync(0xffffffffu, ss, d);
    if (lane == 0) out[b] = (C2 + lg2f_(ss)) * LN2;
}

extern "C" void kernel_launch(void* const* d_in, const int* in_sizes, int n_in,
                              void* d_out, int out_size) {
    const float* feats = nullptr;
    const float* maskp = nullptr;
    const float* trans = nullptr;
    for (int i = 0; i < n_in; ++i) {
        if (in_sizes[i] == SEQ * BATCH * NTAG)      feats = (const float*)d_in[i];
        else if (in_sizes[i] == SEQ * BATCH)        maskp = (const float*)d_in[i];
        else if (in_sizes[i] == NTAG * NTAG)        trans = (const float*)d_in[i];
    }
    crf_main<<<BATCH / 4, 128>>>(feats, maskp, trans, (float*)d_out);
}

// round 12
// speedup vs baseline: 1.4226x; 1.0285x over previous
#include <cuda_runtime.h>
#include <cstdint>

#define SEQ    512
#define BATCH  1024
#define NTAG   64

__device__ __forceinline__ float ex2f_(float x) {
    float y; asm("ex2.approx.ftz.f32 %0, %1;" : "=f"(y) : "f"(x)); return y;
}
__device__ __forceinline__ float lg2f_(float x) {
    float y; asm("lg2.approx.ftz.f32 %0, %1;" : "=f"(y) : "f"(x)); return y;
}
__device__ __forceinline__ unsigned long long fma2_(unsigned long long a,
                                                    unsigned long long b,
                                                    unsigned long long c) {
    unsigned long long d;
    asm("fma.rn.f32x2 %0, %1, %2, %3;" : "=l"(d) : "l"(a), "l"(b), "l"(c));
    return d;
}
__device__ __forceinline__ unsigned long long add2_(unsigned long long a,
                                                    unsigned long long b) {
    unsigned long long d;
    asm("add.rn.f32x2 %0, %1, %2;" : "=l"(d) : "l"(a), "l"(b));
    return d;
}
__device__ __forceinline__ void unpack_(unsigned long long v, float& x, float& y) {
    asm("mov.b64 {%0, %1}, %2;" : "=f"(x), "=f"(y) : "l"(v));
}
__device__ __forceinline__ unsigned long long packf_(float x, float y) {
    unsigned long long r;
    asm("mov.b64 %0, {%1, %2};" : "=l"(r) : "f"(x), "f"(y));
    return r;
}
// bf16x2 word from two fp32 (a -> high half, b -> low half)
__device__ __forceinline__ uint32_t bfpack_(float hi, float lo) {
    uint32_t r;
    asm("cvt.rn.satfinite.bf16x2.f32 %0, %1, %2;" : "=r"(r) : "f"(hi), "f"(lo));
    return r;
}
// expand bf16x2 word into f32x2 operand (low bf16 -> low f32 lane, high -> high)
__device__ __forceinline__ unsigned long long bfexpand_(uint32_t q) {
    const uint32_t lo = q << 16;
    const uint32_t hi = q & 0xffff0000u;
    unsigned long long v;
    asm("mov.b64 %0, {%1, %2};" : "=l"(v) : "r"(lo), "r"(hi));
    return v;
}
__device__ __forceinline__ float wmax_(float v) {
#pragma unroll
    for (int d = 16; d; d >>= 1)
        v = fmaxf(v, __shfl_xor_sync(0xffffffffu, v, d));
    return v;
}

// One warp = one batch, 4 warps/CTA, no smem in the hot loop.
// LINEAR-space recurrence p' = e^{f-SH} ∘ (E p), log2 ledger C2 (R8 math),
// butterfly all-to-all (R11), NOW with:
//   - p transported as ONE bf16x2 word  -> 32 SHFL/step (was 64)
//   - matvec in f32x2 FFMA2             -> 64 FFMA2/step (was 128 FFMA)
// Per round r: q = shfl_xor(pk, r) carries (p[i], p[i+32]), i = lane^r;
// expand to f32x2 v = (p_i, p_{i+32}); acc_lo += (E[j][i],E[j][i+32]) * v,
// acc_hi likewise for j = lane+32. bf16 rounding of the transported p is
// unbiased (rn) -> random-walk ~0.03 absolute in log space over 384 steps.
__global__ void __launch_bounds__(128)
crf_main(const float* __restrict__ feats,
         const float* __restrict__ mask,
         const float* __restrict__ trans,
         float* __restrict__ out) {
    const int lane = threadIdx.x & 31;
    const int w    = threadIdx.x >> 5;
    const int b    = blockIdx.x * 4 + w;

    const float LN2 = 0.6931471805599453f;
    const float L2E = 1.4426950408889634f;
    const float SH2 = 6.0f * L2E;             // constant per-step down-scale (log2)

    // ---- feats pipeline: ready e^{f-SH} (steps 0..3) + raw f (4..7) ----
    const float* fs    = feats + (size_t)b * NTAG + lane;   // step s at +s*65536
    const float* flast = fs + ((size_t)(SEQ - 1) << 16);
    float efL[4], efH[4], fL[4], fH[4];
#pragma unroll
    for (int u = 0; u < 4; ++u) {
        const float* p0 = fs + ((size_t)u << 16);
        efL[u] = ex2f_(fmaf(__ldcs(p0),      L2E, -SH2));
        efH[u] = ex2f_(fmaf(__ldcs(p0 + 32), L2E, -SH2));
        const float* p1 = fs + ((size_t)(u + 4) << 16);
        fL[u] = __ldcs(p1);
        fH[u] = __ldcs(p1 + 32);
    }
    const float* fpre = fs + ((size_t)8 << 16);

    // ---- len = sum of this batch's monotone mask column ----
    float lsum = 0.0f;
#pragma unroll
    for (int t = 0; t < 16; ++t)
        lsum += __ldcs(mask + (size_t)(t * 32 + lane) * BATCH + b);
#pragma unroll
    for (int d = 16; d; d >>= 1)
        lsum += __shfl_xor_sync(0xffffffffu, lsum, d);
    const int len  = (int)(lsum + 0.5f);
    const int lenr = (len + 3) & ~3;

    // ---- E pre-permuted + pre-packed for the butterfly ----
    // EAC[r] = ( exp(T[lane   ][i]), exp(T[lane   ][32+i]) ), i = lane^r
    // EBD[r] = ( exp(T[lane+32][i]), exp(T[lane+32][32+i]) )
    unsigned long long EAC[32], EBD[32];
#pragma unroll
    for (int r = 0; r < 32; ++r) {
        const int i = lane ^ r;
        EAC[r] = packf_(__expf(__ldg(trans + lane * NTAG + i)),        // ->0 on START row
                        __expf(__ldg(trans + lane * NTAG + 32 + i)));
        EBD[r] = packf_(__expf(__ldg(trans + (lane + 32) * NTAG + i)),
                        __expf(__ldg(trans + (lane + 32) * NTAG + 32 + i)));
    }
    const float eT_lo = ex2f_(trans[NTAG + lane] * L2E);         // exp(T[END][j])
    const float eT_hi = ex2f_(trans[NTAG + 32 + lane] * L2E);

    // ---- linear-space state (registers only) ----
    float p_lo = (lane == 0) ? 1.0f : 0.0f;   // p = exp(alpha0), START=0
    float p_hi = 0.0f;
    float C2   = 0.0f;                        // alpha = (log2 p + C2) * ln2
    float rfac = 1.0f;                        // renorm scale, applied at u==2
    float lgMp = 0.0f;                        // its lg2(M) ledger entry
    uint32_t pk = bfpack_(p_hi, p_lo);        // transport word

#pragma unroll 1
    for (int s = 0; s < lenr; s += 4) {
#pragma unroll
        for (int u = 0; u < 4; ++u) {
            // S = E p via 32 butterflies: 32 SHFL + 64 ALU + 64 FFMA2
            unsigned long long a0 = 0ull, a1 = 0ull;   // S_lo partial pairs
            unsigned long long b0 = 0ull, b1 = 0ull;   // S_hi partial pairs
#pragma unroll
            for (int r = 0; r < 32; r += 2) {
                const unsigned long long v0 =
                    bfexpand_(__shfl_xor_sync(0xffffffffu, pk, r));
                a0 = fma2_(EAC[r], v0, a0);
                b0 = fma2_(EBD[r], v0, b0);
                const unsigned long long v1 =
                    bfexpand_(__shfl_xor_sync(0xffffffffu, pk, r + 1));
                a1 = fma2_(EAC[r + 1], v1, a1);
                b1 = fma2_(EBD[r + 1], v1, b1);
            }
            float sa0, sa1, sb0, sb1;
            unpack_(add2_(a0, a1), sa0, sa1);
            unpack_(add2_(b0, b1), sb0, sb1);
            const float S_lo = sa0 + sa1;
            const float S_hi = sb0 + sb1;

            // p' = e^{f-SH} ∘ S, renorm folded in at substep 2 only
            const bool  upd = (s + u) < len;
            const float rr  = (u == 2) ? rfac : 1.0f;
            const float n_lo = S_lo * (efL[u] * rr);
            const float n_hi = S_hi * (efH[u] * rr);
            p_lo = upd ? n_lo : p_lo;
            p_hi = upd ? n_hi : p_hi;
            C2   = upd ? (C2 + SH2 + ((u == 2) ? lgMp : 0.0f)) : C2;
            pk   = bfpack_(p_hi, p_lo);       // next transport word

            // off-chain: feats pipeline (consumed 4 substeps later)
            efL[u] = ex2f_(fmaf(fL[u], L2E, -SH2));
            efH[u] = ex2f_(fmaf(fH[u], L2E, -SH2));
            const float* pf = (fpre <= flast) ? fpre : flast;
            fL[u] = __ldcs(pf);
            fH[u] = __ldcs(pf + 32);
            fpre += (size_t)1 << 16;

            // once per 4 steps: renorm measured here, applied next block @u==2
            if (u == 3) {
                const float M   = fmaxf(wmax_(fmaxf(p_lo, p_hi)), 1e-30f);
                const float lgM = lg2f_(M);
                rfac = ex2f_(-lgM);
                lgMp = lgM;
            }
        }
    }

    // out[b] = (C2 + lg2( sum_j p_j * exp(T[END][j]) )) * ln2
    float ss = p_lo * eT_lo + p_hi * eT_hi;
#pragma unroll
    for (int d = 16; d; d >>= 1)
        ss += __shfl_xor_sync(0xffffffffu, ss, d);
    if (lane == 0) out[b] = (C2 + lg2f_(ss)) * LN2;
}

extern "C" void kernel_launch(void* const* d_in, const int* in_sizes, int n_in,
                              void* d_out, int out_size) {
    const float* feats = nullptr;
    const float* maskp = nullptr;
    const float* trans = nullptr;
    for (int i = 0; i < n_in; ++i) {
        if (in_sizes[i] == SEQ * BATCH * NTAG)      feats = (const float*)d_in[i];
        else if (in_sizes[i] == SEQ * BATCH)        maskp = (const float*)d_in[i];
        else if (in_sizes[i] == NTAG * NTAG)        trans = (const float*)d_in[i];
    }
    crf_main<<<BATCH / 4, 128>>>(feats, maskp, trans, (float*)d_out);
}

// round 13
// speedup vs baseline: 1.4900x; 1.0474x over previous
#include <cuda_runtime.h>
#include <cstdint>

#define SEQ    512
#define BATCH  1024
#define NTAG   64

__device__ __forceinline__ float ex2f_(float x) {
    float y; asm("ex2.approx.ftz.f32 %0, %1;" : "=f"(y) : "f"(x)); return y;
}
__device__ __forceinline__ float lg2f_(float x) {
    float y; asm("lg2.approx.ftz.f32 %0, %1;" : "=f"(y) : "f"(x)); return y;
}
__device__ __forceinline__ unsigned long long fma2_(unsigned long long a,
                                                    unsigned long long b,
                                                    unsigned long long c) {
    unsigned long long d;
    asm("fma.rn.f32x2 %0, %1, %2, %3;" : "=l"(d) : "l"(a), "l"(b), "l"(c));
    return d;
}
__device__ __forceinline__ unsigned long long add2_(unsigned long long a,
                                                    unsigned long long b) {
    unsigned long long d;
    asm("add.rn.f32x2 %0, %1, %2;" : "=l"(d) : "l"(a), "l"(b));
    return d;
}
__device__ __forceinline__ void unpack_(unsigned long long v, float& x, float& y) {
    asm("mov.b64 {%0, %1}, %2;" : "=f"(x), "=f"(y) : "l"(v));
}
__device__ __forceinline__ unsigned long long packf_(float x, float y) {
    unsigned long long r;
    asm("mov.b64 %0, {%1, %2};" : "=l"(r) : "f"(x), "f"(y));
    return r;
}
__device__ __forceinline__ uint32_t bfpack_(float hi, float lo) {
    uint32_t r;
    asm("cvt.rn.satfinite.bf16x2.f32 %0, %1, %2;" : "=r"(r) : "f"(hi), "f"(lo));
    return r;
}
__device__ __forceinline__ unsigned long long bfexpand_(uint32_t q) {
    const uint32_t lo = q << 16;
    const uint32_t hi = q & 0xffff0000u;
    unsigned long long v;
    asm("mov.b64 %0, {%1, %2};" : "=l"(v) : "r"(lo), "r"(hi));
    return v;
}
__device__ __forceinline__ float wmax_(float v) {
#pragma unroll
    for (int d = 16; d; d >>= 1)
        v = fmaxf(v, __shfl_xor_sync(0xffffffffu, v, d));
    return v;
}

// One CTA = 64 threads = ONE batch:
//   warp 0 (fwd):  p_{t+1} = e^{f_t-SH} ∘ (E p_t),        t = 0 .. h-1
//   warp 1 (bwd):  z_t     = E^T (e^{f_t-SH} ∘ z_{t+1}),  t = len-1 .. h
// out = (C2f + C2b + lg2 <p_h, z_h>) * ln2  — exact identity.
// Engine per warp = R12 butterfly: register-only, 32 SHFL(bf16x2 transport)
// + 64 FFMA2 per step, renorm once per 4 steps with 3 substeps of slack.
// NO launch_bounds occupancy clamp: the E table (128 regs) must not spill
// (that spill is what sank R10).
__global__ void __launch_bounds__(64)
crf_main(const float* __restrict__ feats,
         const float* __restrict__ mask,
         const float* __restrict__ trans,
         float* __restrict__ out) {
    const int lane = threadIdx.x & 31;
    const int dir  = threadIdx.x >> 5;        // 0 = forward, 1 = backward
    const int b    = blockIdx.x;

    __shared__ float vf[2][NTAG];             // final vectors (combine only)
    __shared__ float c2s[2];

    const float LN2 = 0.6931471805599453f;
    const float L2E = 1.4426950408889634f;
    const float SH2 = 6.0f * L2E;             // constant per-step down-scale

    // ---- len = sum of this batch's monotone mask column ----
    float lsum = 0.0f;
#pragma unroll
    for (int t = 0; t < 16; ++t)
        lsum += __ldcs(mask + (size_t)(t * 32 + lane) * BATCH + b);
#pragma unroll
    for (int d = 16; d; d >>= 1)
        lsum += __shfl_xor_sync(0xffffffffu, lsum, d);
    const int len = (int)(lsum + 0.5f);
    const int h   = (len + 1) >> 1;
    const int nst = dir ? (len - h) : h;      // my step count (>=128)
    const int lenr = (nst + 3) & ~3;

    // ---- pre-permuted, pre-packed coefficient table ----
    // coeff(out j, in i) = exp(trans[j*s1 + i*s2]); fwd s1=64,s2=1; bwd E^T.
    const int s1 = dir ? 1 : NTAG;
    const int s2 = dir ? NTAG : 1;
    unsigned long long Elo[32], Ehi[32];      // out = lane / lane+32
#pragma unroll
    for (int r = 0; r < 32; ++r) {
        const int i = lane ^ r;
        Elo[r] = packf_(__expf(__ldg(trans + lane * s1 + i * s2)),
                        __expf(__ldg(trans + lane * s1 + (32 + i) * s2)));
        Ehi[r] = packf_(__expf(__ldg(trans + (lane + 32) * s1 + i * s2)),
                        __expf(__ldg(trans + (lane + 32) * s1 + (32 + i) * s2)));
    }

    // ---- feats pipeline (direction-dependent stream) ----
    const float* fs = feats + (size_t)b * NTAG + lane;   // step s at +s*65536
    const int f0    = dir ? len - 2 : 0;
    const int dstep = dir ? -1 : 1;
    float efL[4], efH[4], fL[4], fH[4];
#pragma unroll
    for (int u = 0; u < 4; ++u) {
        const float* p0 = fs + ((size_t)(f0 + dstep * u) << 16);
        efL[u] = ex2f_(fmaf(__ldcs(p0),      L2E, -SH2));
        efH[u] = ex2f_(fmaf(__ldcs(p0 + 32), L2E, -SH2));
        const float* p1 = fs + ((size_t)(f0 + dstep * (u + 4)) << 16);
        fL[u] = __ldcs(p1);
        fH[u] = __ldcs(p1 + 32);
    }
    int fidx = f0 + dstep * 8;                // remains within [0, SEQ-1]

    // ---- initial state + transport word ----
    float st_lo, st_hi;
    uint32_t pk;
    if (dir == 0) {                            // p_0 = one-hot at START=0
        st_lo = (lane == 0) ? 1.0f : 0.0f;
        st_hi = 0.0f;
        pk = bfpack_(st_hi, st_lo);
    } else {                                   // w = e^{f_{len-1}-SH} ∘ z_len
        const float z_lo = __expf(trans[NTAG + lane]);        // exp(T[END][i])
        const float z_hi = __expf(trans[NTAG + 32 + lane]);
        const float* pl = fs + ((size_t)(len - 1) << 16);
        const float w_lo = z_lo * ex2f_(fmaf(__ldcs(pl),      L2E, -SH2));
        const float w_hi = z_hi * ex2f_(fmaf(__ldcs(pl + 32), L2E, -SH2));
        st_lo = z_lo; st_hi = z_hi;
        pk = bfpack_(w_hi, w_lo);
    }

    float C2 = 0.0f, rfac = 1.0f, lgMp = 0.0f;

#pragma unroll 1
    for (int s = 0; s < lenr; s += 4) {
#pragma unroll
        for (int u = 0; u < 4; ++u) {
            // S = coeff · (shfl'd vector): 32 SHFL + 64 expand + 64 FFMA2
            unsigned long long a0 = 0ull, a1 = 0ull;
            unsigned long long b0 = 0ull, b1 = 0ull;
#pragma unroll
            for (int r = 0; r < 32; r += 2) {
                const unsigned long long v0 =
                    bfexpand_(__shfl_xor_sync(0xffffffffu, pk, r));
                a0 = fma2_(Elo[r], v0, a0);
                b0 = fma2_(Ehi[r], v0, b0);
                const unsigned long long v1 =
                    bfexpand_(__shfl_xor_sync(0xffffffffu, pk, r + 1));
                a1 = fma2_(Elo[r + 1], v1, a1);
                b1 = fma2_(Ehi[r + 1], v1, b1);
            }
            float sa0, sa1, sb0, sb1;
            unpack_(add2_(a0, a1), sa0, sa1);
            unpack_(add2_(b0, b1), sb0, sb1);

            const bool  upd = (s + u) < nst;
            const float rr  = (u == 2) ? rfac : 1.0f;
            const float Sr_lo = (sa0 + sa1) * rr;
            const float Sr_hi = (sb0 + sb1) * rr;
            const float pub_lo = Sr_lo * efL[u];   // next transported vector
            const float pub_hi = Sr_hi * efH[u];
            // fwd state = post-ef vector (p); bwd state = pure S (z)
            const float cd_lo = dir ? Sr_lo : pub_lo;
            const float cd_hi = dir ? Sr_hi : pub_hi;
            st_lo = upd ? cd_lo : st_lo;
            st_hi = upd ? cd_hi : st_hi;
            C2 = upd ? (C2 + SH2 + ((u == 2) ? lgMp : 0.0f)) : C2;
            pk = bfpack_(pub_hi, pub_lo);

            // off-chain: feats pipeline (consumed 4 substeps later)
            efL[u] = ex2f_(fmaf(fL[u], L2E, -SH2));
            efH[u] = ex2f_(fmaf(fH[u], L2E, -SH2));
            int fi = fidx;
            fi = fi < 0 ? 0 : (fi > SEQ - 1 ? SEQ - 1 : fi);
            const float* pf = fs + ((size_t)fi << 16);
            fL[u] = __ldcs(pf);
            fH[u] = __ldcs(pf + 32);
            fidx += dstep;

            // once per 4 steps: renorm measured, applied next block @u==2
            if (u == 3) {
                const float M   = fmaxf(wmax_(fmaxf(pub_lo, pub_hi)), 1e-30f);
                const float lgM = lg2f_(M);
                rfac = ex2f_(-lgM);
                lgMp = lgM;
            }
        }
    }

    // ---- combine: out = (C2f + C2b + lg2 <p_h, z_h>) * ln2 ----
    vf[dir][lane]      = st_lo;
    vf[dir][lane + 32] = st_hi;
    if (lane == 0) c2s[dir] = C2;
    __syncthreads();
    if (dir == 0) {
        float ss = st_lo * vf[1][lane] + st_hi * vf[1][lane + 32];
#pragma unroll
        for (int d = 16; d; d >>= 1)
            ss += __shfl_xor_sync(0xffffffffu, ss, d);
        if (lane == 0)
            out[b] = (c2s[0] + c2s[1] + lg2f_(ss)) * LN2;
    }
}

extern "C" void kernel_launch(void* const* d_in, const int* in_sizes, int n_in,
                              void* d_out, int out_size) {
    const float* feats = nullptr;
    const float* maskp = nullptr;
    const float* trans = nullptr;
    for (int i = 0; i < n_in; ++i) {
        if (in_sizes[i] == SEQ * BATCH * NTAG)      feats = (const float*)d_in[i];
        else if (in_sizes[i] == SEQ * BATCH)        maskp = (const float*)d_in[i];
        else if (in_sizes[i] == NTAG * NTAG)        trans = (const float*)d_in[i];
    }
    crf_main<<<BATCH, 64>>>(feats, maskp, trans, (float*)d_out);
}